// round 8
// baseline (speedup 1.0000x reference)
#include <cuda_runtime.h>
#include <cuda_bf16.h>
#include <math.h>

#define T_ 256
#define B_ 16
#define E_ 512
#define H_ 2048
#define N_ 14839
#define U_ 48
#define G4H 8192
#define KA 2560              /* combined act length: 512 ctx + 2048 h */
#define EPS_ 1e-6f
#define NT 256
#define GRID 296

/* ---------------- scratch ---------------- */
__device__ float g_xh_m[T_*B_*E_];
__device__ float g_xh_c[T_*B_*E_];
__device__ float g_emb[U_*B_*E_];
__device__ float g_eg[(size_t)U_*B_*G4H];
__device__ float g_gp[2][(size_t)B_*G4H];     /* k-split partial gates */
__device__ float g_h[2][B_*H_];
__device__ float g_c[2][B_*H_];
__device__ float g_alpha[2][T_*B_];
__device__ float g_sm[B_*E_];
__device__ float g_sc[B_*E_];
__device__ float g_p[T_*B_];
__device__ float g_u[T_*B_];
__device__ float g_scall[U_*B_*2*E_];
__device__ float g_wpT[H_*E_];
__device__ float g_comb[2*E_*H_];
__device__ __nv_bfloat16 g_wcomb[(size_t)G4H*KA];  /* [Wih_ctx | Whh] bf16 */
__device__ __nv_bfloat16 g_actbf[B_*KA];           /* [ctx | h] bf16 */

/* grid barrier state */
__device__ unsigned g_cnt = 0;
__device__ volatile unsigned g_gen = 0;

__device__ __forceinline__ void gbar() {
    __syncthreads();
    if (threadIdx.x == 0) {
        unsigned gen = g_gen;
        __threadfence();
        if (atomicAdd(&g_cnt, 1u) == gridDim.x - 1u) {
            g_cnt = 0;
            __threadfence();
            g_gen = gen + 1u;
        } else {
            while (g_gen == gen) __nanosleep(32);
        }
        __threadfence();
    }
    __syncthreads();
}

__device__ __forceinline__ float sigm(float x) { return 1.f / (1.f + expf(-x)); }
__device__ __forceinline__ float tanha(float x) {
    float y; asm("tanh.approx.f32 %0, %1;" : "=f"(y) : "f"(x)); return y;
}
__device__ __forceinline__ unsigned tf32c(float x) {
    unsigned r; asm("cvt.rna.tf32.f32 %0, %1;" : "=r"(r) : "f"(x)); return r;
}

/* ---------------- init ---------------- */
__global__ void init_state(float* h, float* c, float* alpha, __nv_bfloat16* actbf) {
    int i = blockIdx.x * blockDim.x + threadIdx.x;
    if (i < 2*B_*H_) { h[i] = 0.f; c[i] = 0.f; }
    if (i < B_*KA)   actbf[i] = __float2bfloat16(0.f);
    if (i < T_*B_)   alpha[i] = (i < B_) ? 1.f : 0.f;
}

/* ---------------- combined bf16 weight build ---------------- */
__global__ void build_wcomb(const float* __restrict__ W_ih, const float* __restrict__ W_hh,
                            __nv_bfloat16* __restrict__ wc) {
    size_t i = (size_t)blockIdx.x * blockDim.x + threadIdx.x;
    if (i >= (size_t)G4H * KA) return;
    int r = (int)(i / KA), k = (int)(i % KA);
    float v = (k < E_) ? W_ih[(size_t)r * (2*E_) + E_ + k]
                       : W_hh[(size_t)r * H_ + (k - E_)];
    wc[i] = __float2bfloat16(v);
}

/* ---------------- embedding gather ---------------- */
__global__ void gather_emb(const float* __restrict__ emb_table,
                           const int* __restrict__ label,
                           float* __restrict__ emb) {
    int r = blockIdx.x;
    int n = label[r];
    const float* src = emb_table + (size_t)n * E_;
    float* dst = emb + (size_t)r * E_;
    for (int i = threadIdx.x; i < E_; i += blockDim.x) dst[i] = src[i];
}

/* ---------------- transpose (512,2048) -> (2048,512) ---------------- */
__global__ void transposeEH(const float* __restrict__ A, float* __restrict__ At) {
    __shared__ float tile[32][33];
    int x0 = blockIdx.x * 32, y0 = blockIdx.y * 32;
    int tx = threadIdx.x, ty = threadIdx.y;
    for (int j = 0; j < 32; j += 8)
        tile[ty+j][tx] = A[(size_t)(y0+ty+j) * H_ + x0 + tx];
    __syncthreads();
    for (int j = 0; j < 32; j += 8)
        At[(size_t)(x0+ty+j) * E_ + y0 + tx] = tile[tx][ty+j];
}

/* ============ tf32 tensor-core GEMM (verified in R7) ============ */
#define TKC 32
#define TKP (TKC+4)
__global__ __launch_bounds__(256) void tgemm_tn(
        const float* __restrict__ W, int ldw,
        const float* __restrict__ X, int ldx,
        const float* __restrict__ bias,
        float* __restrict__ C, size_t ldcw, size_t ldcx,
        int M, int Nx, int K)
{
    __shared__ unsigned Ws[128][TKP];
    __shared__ unsigned Xs[64][TKP];
    int tid = threadIdx.x;
    int wid = tid >> 5, lane = tid & 31;
    int wm = (wid & 3) * 32;
    int wn = (wid >> 2) * 32;
    int m0 = blockIdx.y * 128;
    int n0 = blockIdx.x * 64;
    int g = lane >> 2, t = lane & 3;

    float c[2][4][4];
#pragma unroll
    for (int i = 0; i < 2; i++)
#pragma unroll
        for (int j = 0; j < 4; j++)
#pragma unroll
            for (int q = 0; q < 4; q++) c[i][j][q] = 0.f;

    for (int k0 = 0; k0 < K; k0 += TKC) {
        {
            int r = tid >> 1;
            int cc = (tid & 1) * 16;
#pragma unroll
            for (int i = 0; i < 4; i++) {
                float4 v = make_float4(0.f,0.f,0.f,0.f);
                if (m0 + r < M)
                    v = *(const float4*)(W + (size_t)(m0 + r) * ldw + k0 + cc + i*4);
                Ws[r][cc+i*4+0] = tf32c(v.x); Ws[r][cc+i*4+1] = tf32c(v.y);
                Ws[r][cc+i*4+2] = tf32c(v.z); Ws[r][cc+i*4+3] = tf32c(v.w);
            }
        }
        {
            int r = tid >> 2;
            int cc = (tid & 3) * 8;
#pragma unroll
            for (int i = 0; i < 2; i++) {
                float4 v = make_float4(0.f,0.f,0.f,0.f);
                if (n0 + r < Nx)
                    v = *(const float4*)(X + (size_t)(n0 + r) * ldx + k0 + cc + i*4);
                Xs[r][cc+i*4+0] = tf32c(v.x); Xs[r][cc+i*4+1] = tf32c(v.y);
                Xs[r][cc+i*4+2] = tf32c(v.z); Xs[r][cc+i*4+3] = tf32c(v.w);
            }
        }
        __syncthreads();

#pragma unroll
        for (int kk = 0; kk < TKC; kk += 8) {
            unsigned a[2][4];
#pragma unroll
            for (int mt = 0; mt < 2; mt++) {
                int br = wm + mt*16;
                a[mt][0] = Ws[br + g    ][kk + t];
                a[mt][1] = Ws[br + g + 8][kk + t];
                a[mt][2] = Ws[br + g    ][kk + t + 4];
                a[mt][3] = Ws[br + g + 8][kk + t + 4];
            }
            unsigned b[4][2];
#pragma unroll
            for (int nt = 0; nt < 4; nt++) {
                b[nt][0] = Xs[wn + nt*8 + g][kk + t];
                b[nt][1] = Xs[wn + nt*8 + g][kk + t + 4];
            }
#pragma unroll
            for (int mt = 0; mt < 2; mt++)
#pragma unroll
                for (int nt = 0; nt < 4; nt++) {
                    asm volatile(
                        "mma.sync.aligned.m16n8k8.row.col.f32.tf32.tf32.f32 "
                        "{%0,%1,%2,%3}, {%4,%5,%6,%7}, {%8,%9}, {%0,%1,%2,%3};"
                        : "+f"(c[mt][nt][0]), "+f"(c[mt][nt][1]),
                          "+f"(c[mt][nt][2]), "+f"(c[mt][nt][3])
                        : "r"(a[mt][0]), "r"(a[mt][1]), "r"(a[mt][2]), "r"(a[mt][3]),
                          "r"(b[nt][0]), "r"(b[nt][1]));
                }
        }
        __syncthreads();
    }

#pragma unroll
    for (int mt = 0; mt < 2; mt++) {
#pragma unroll
        for (int nt = 0; nt < 4; nt++) {
            int row0 = m0 + wm + mt*16 + g;
            int col0 = n0 + wn + nt*8 + 2*t;
#pragma unroll
            for (int half = 0; half < 2; half++) {
                int row = row0 + half*8;
                if (row >= M) continue;
                float bv = bias ? bias[row] : 0.f;
                if (col0 < Nx)
                    C[(size_t)row*ldcw + (size_t)col0*ldcx] = c[mt][nt][half*2+0] + bv;
                if (col0 + 1 < Nx)
                    C[(size_t)row*ldcw + (size_t)(col0+1)*ldcx] = c[mt][nt][half*2+1] + bv;
            }
        }
    }
}

/* ================ PERSISTENT DECODER LOOP ================ */
__global__ __launch_bounds__(NT) void decoder_loop(
        const float* __restrict__ x, const float* __restrict__ mask,
        const __nv_bfloat16* __restrict__ wcomb,
        const float* __restrict__ wproj, const float* __restrict__ comb,
        const float* __restrict__ eg,
        const float* __restrict__ v_m, const float* __restrict__ v_c,
        const float* __restrict__ r_m,
        const float* __restrict__ xh_m, const float* __restrict__ xh_c,
        float* gp, float* hb, float* cb, float* alb,
        __nv_bfloat16* actbf,
        float* smv, float* scv, float* pv, float* uvv,
        float* scall)
{
    __shared__ float shA[T_], shB[T_], shC[T_], shD[T_], shR[T_], shBeta[T_];
    int tid = threadIdx.x;
    int lane = tid & 31;
    int gw = blockIdx.x * (NT/32) + (tid >> 5);
    int NW = gridDim.x * (NT/32);
    int gtid = blockIdx.x * NT + tid;
    int NTH = gridDim.x * NT;
    int g = lane >> 2, t = lane & 3;

    for (int u = 0; u < U_; u++) {
        float*       h_out = hb + ((u&1)^1)*(B_*H_);
        const float* c_in  = cb + (u&1)*(B_*H_);
        float*       c_out = cb + ((u&1)^1)*(B_*H_);
        const float* al_in  = alb + (u&1)*(T_*B_);
        float*       al_out = alb + ((u&1)^1)*(T_*B_);
        const float* eg_u = eg + (size_t)u*B_*G4H;
        float*       sc_u = scall + (size_t)u*B_*(2*E_);

        /* ---- Phase A: partial gates via bf16 tensor-core MMA ----
           gates[b,n] = sum_k actbf[b,k] * wcomb[n,k]; 1024 n-tiles x k-split 2. */
        for (int job = gw; job < 2048; job += NW) {
            int tile = job >> 1, half = job & 1;
            int n0 = tile * 8;
            int kbeg = half * (KA/2);
            int kend = kbeg + (KA/2);
            float c0 = 0.f, c1 = 0.f, c2 = 0.f, c3 = 0.f;
            const __nv_bfloat16* wr  = wcomb + (size_t)(n0 + g) * KA;
            const __nv_bfloat16* ar0 = actbf + (size_t)g * KA;
            const __nv_bfloat16* ar1 = actbf + (size_t)(g + 8) * KA;
            for (int k0 = kbeg; k0 < kend; k0 += 16) {
                unsigned a0 = *(const unsigned*)(ar0 + k0 + 2*t);
                unsigned a1 = *(const unsigned*)(ar1 + k0 + 2*t);
                unsigned a2 = *(const unsigned*)(ar0 + k0 + 2*t + 8);
                unsigned a3 = *(const unsigned*)(ar1 + k0 + 2*t + 8);
                unsigned b0 = *(const unsigned*)(wr + k0 + 2*t);
                unsigned b1 = *(const unsigned*)(wr + k0 + 2*t + 8);
                asm volatile(
                    "mma.sync.aligned.m16n8k16.row.col.f32.bf16.bf16.f32 "
                    "{%0,%1,%2,%3}, {%4,%5,%6,%7}, {%8,%9}, {%0,%1,%2,%3};"
                    : "+f"(c0), "+f"(c1), "+f"(c2), "+f"(c3)
                    : "r"(a0), "r"(a1), "r"(a2), "r"(a3), "r"(b0), "r"(b1));
            }
            float* gpd = gp + (size_t)half * (B_*G4H);
            gpd[(size_t)g      *G4H + n0 + 2*t    ] = c0;
            gpd[(size_t)g      *G4H + n0 + 2*t + 1] = c1;
            gpd[(size_t)(g + 8)*G4H + n0 + 2*t    ] = c2;
            gpd[(size_t)(g + 8)*G4H + n0 + 2*t + 1] = c3;
        }
        gbar();

        /* ---- Phase B: sum partials + eg, LSTM pointwise; write h (fp32 + bf16) ---- */
        for (int i = gtid; i < B_*H_; i += NTH) {
            int b = i >> 11, k = i & (H_-1);
            size_t base = (size_t)b * G4H;
            const float* g0 = gp;
            const float* g1 = gp + (size_t)(B_*G4H);
            float gi = g0[base + k]        + g1[base + k]        + eg_u[base + k];
            float gf = g0[base + H_ + k]   + g1[base + H_ + k]   + eg_u[base + H_ + k];
            float gg = g0[base + 2*H_ + k] + g1[base + 2*H_ + k] + eg_u[base + 2*H_ + k];
            float go = g0[base + 3*H_ + k] + g1[base + 3*H_ + k] + eg_u[base + 3*H_ + k];
            float cn = sigm(gf) * c_in[i] + sigm(gi) * tanhf(gg);
            c_out[i] = cn;
            float hn = sigm(go) * tanhf(cn);
            h_out[i] = hn;
            actbf[(size_t)b * KA + E_ + k] = __float2bfloat16(hn);
        }
        gbar();

        /* ---- Phase C: s / sm / sc from h_new (fp32) ---- */
        for (int r = gw; r < 3*E_; r += NW) {
            const float* Wr = (r < E_) ? (wproj + (size_t)r * H_)
                                       : (comb + (size_t)(r - E_) * H_);
            float acc[16];
#pragma unroll
            for (int b = 0; b < 16; b++) acc[b] = 0.f;
            for (int k = lane*4; k < H_; k += 128) {
                float4 wv = *(const float4*)(Wr + k);
#pragma unroll
                for (int b = 0; b < 16; b++) {
                    float4 a = *(const float4*)(h_out + (size_t)b*H_ + k);
                    acc[b] += wv.x*a.x + wv.y*a.y + wv.z*a.z + wv.w*a.w;
                }
            }
#pragma unroll
            for (int b = 0; b < 16; b++)
#pragma unroll
                for (int off = 16; off > 0; off >>= 1)
                    acc[b] += __shfl_xor_sync(0xffffffffu, acc[b], off);
            if (lane < 16) {
                float v = acc[lane];
                if (r < E_)            sc_u[lane*(2*E_) + r] = v;
                else if (r < 2*E_)     smv[lane*E_ + (r - E_)] = v;
                else                   scv[lane*E_ + (r - 2*E_)] = v;
            }
        }
        gbar();

        /* ---- Phase D: energies ---- */
        for (int w = gw; w < T_*B_; w += NW) {
            int tt = w >> 4, b = w & 15;
            const float* xmp = xh_m + (size_t)(tt*B_ + b) * E_;
            const float* xcp = xh_c + (size_t)(tt*B_ + b) * E_;
            const float* smp = smv + (size_t)b * E_;
            const float* scp = scv + (size_t)b * E_;
            float am = 0.f, ac = 0.f;
            for (int e = lane*4; e < E_; e += 128) {
                float4 a  = *(const float4*)(xmp + e);
                float4 s4 = *(const float4*)(smp + e);
                float4 v4 = *(const float4*)(v_m + e);
                am += v4.x*tanha(a.x+s4.x) + v4.y*tanha(a.y+s4.y)
                    + v4.z*tanha(a.z+s4.z) + v4.w*tanha(a.w+s4.w);
                float4 a2  = *(const float4*)(xcp + e);
                float4 s42 = *(const float4*)(scp + e);
                float4 v42 = *(const float4*)(v_c + e);
                ac += v42.x*tanha(a2.x+s42.x) + v42.y*tanha(a2.y+s42.y)
                    + v42.z*tanha(a2.z+s42.z) + v42.w*tanha(a2.w+s42.w);
            }
#pragma unroll
            for (int off = 16; off > 0; off >>= 1) {
                am += __shfl_xor_sync(0xffffffffu, am, off);
                ac += __shfl_xor_sync(0xffffffffu, ac, off);
            }
            if (lane == 0) {
                float mk = mask[b*T_ + tt];
                pv[tt*B_ + b] = sigm(am + r_m[0]) * mk;
                uvv[tt*B_ + b] = ac;
            }
        }
        gbar();

        /* ---- Phase E+F: per-b scans then ctx (blocks 0..15) ---- */
        if (blockIdx.x < B_) {
            int b = blockIdx.x, tt = tid;
            float pvv = pv[tt*B_ + b];
            float uvl = uvv[tt*B_ + b];
            float ap  = al_in[tt*B_ + b];
            float mk  = mask[b*T_ + tt];

            shR[tt] = uvl; __syncthreads();
            for (int off = 128; off > 0; off >>= 1) {
                if (tt < off) shR[tt] = fmaxf(shR[tt], shR[tt+off]);
                __syncthreads();
            }
            float um = shR[0];

            float eu = expf(uvl - um) * mk;
            shA[tt] = eu; __syncthreads();
#pragma unroll
            for (int off = 1; off < T_; off <<= 1) {
                float xv = (tt >= off) ? shA[tt-off] : 0.f;
                __syncthreads(); shA[tt] += xv; __syncthreads();
            }
            float denom = shA[tt] - (tt >= 8 ? shA[tt-8] : 0.f);

            shB[tt] = 1.f - pvv; __syncthreads();
#pragma unroll
            for (int off = 1; off < T_; off <<= 1) {
                float xv = (tt >= off) ? shB[tt-off] : 1.f;
                __syncthreads(); shB[tt] *= xv; __syncthreads();
            }
            float cp = (tt == 0) ? 1.f : shB[tt-1];

            shC[tt] = ap / fmaxf(cp, EPS_); __syncthreads();
#pragma unroll
            for (int off = 1; off < T_; off <<= 1) {
                float xv = (tt >= off) ? shC[tt-off] : 0.f;
                __syncthreads(); shC[tt] += xv; __syncthreads();
            }
            float av = pvv * cp * shC[tt];

            shD[tt] = av / fmaxf(denom, EPS_); __syncthreads();
#pragma unroll
            for (int off = 1; off < T_; off <<= 1) {
                float xv = (tt >= off) ? shD[tt-off] : 0.f;
                __syncthreads(); shD[tt] += xv; __syncthreads();
            }
            int hi = (tt + 7 > T_-1) ? (T_-1) : (tt + 7);
            float bv = eu * (shD[hi] - (tt > 0 ? shD[tt-1] : 0.f));

            al_out[tt*B_ + b] = av;
            shBeta[tt] = bv;
            __syncthreads();

            /* ctx for this b: E_ over 256 threads (2 each) */
            for (int d = tid; d < E_; d += NT) {
                const float* xp = x + (size_t)b*E_ + d;
                float acc = 0.f;
#pragma unroll 8
                for (int q = 0; q < T_; q++)
                    acc += shBeta[q] * xp[(size_t)q * B_ * E_];
                sc_u[(size_t)b*(2*E_) + E_ + d] = acc;
                actbf[(size_t)b * KA + d] = __float2bfloat16(acc);
            }
        }
        gbar();
    }
}

/* ---------------- host launcher ---------------- */
extern "C" void kernel_launch(void* const* d_in, const int* in_sizes, int n_in,
                              void* d_out, int out_size)
{
    const float* x        = (const float*)d_in[0];
    const float* att_mask = (const float*)d_in[1];
    const float* emb_tab  = (const float*)d_in[2];
    const float* W_ih     = (const float*)d_in[3];
    const float* W_hh     = (const float*)d_in[4];
    const float* b_lstm   = (const float*)d_in[5];
    const float* W_proj   = (const float*)d_in[6];
    const float* Ws_m     = (const float*)d_in[7];
    const float* Wh_m     = (const float*)d_in[8];
    const float* v_m      = (const float*)d_in[9];
    const float* r_m      = (const float*)d_in[10];
    const float* Ws_c     = (const float*)d_in[11];
    const float* Wh_c     = (const float*)d_in[12];
    const float* v_c      = (const float*)d_in[13];
    const float* W_am     = (const float*)d_in[14];
    const float* W_lm     = (const float*)d_in[15];
    const int*   label    = (const int*)d_in[16];

    float* out_am = (float*)d_out;
    float* out_lm = out_am + (size_t)N_ * U_ * B_;

    float *xh_m, *xh_c, *emb, *eg, *gp, *hb, *cb, *alb, *sm, *sc, *p, *uu, *scall, *wpT, *comb;
    __nv_bfloat16 *wcomb, *actbf;
    cudaGetSymbolAddress((void**)&xh_m,  g_xh_m);
    cudaGetSymbolAddress((void**)&xh_c,  g_xh_c);
    cudaGetSymbolAddress((void**)&emb,   g_emb);
    cudaGetSymbolAddress((void**)&eg,    g_eg);
    cudaGetSymbolAddress((void**)&gp,    g_gp);
    cudaGetSymbolAddress((void**)&hb,    g_h);
    cudaGetSymbolAddress((void**)&cb,    g_c);
    cudaGetSymbolAddress((void**)&alb,   g_alpha);
    cudaGetSymbolAddress((void**)&sm,    g_sm);
    cudaGetSymbolAddress((void**)&sc,    g_sc);
    cudaGetSymbolAddress((void**)&p,     g_p);
    cudaGetSymbolAddress((void**)&uu,    g_u);
    cudaGetSymbolAddress((void**)&scall, g_scall);
    cudaGetSymbolAddress((void**)&wpT,   g_wpT);
    cudaGetSymbolAddress((void**)&comb,  g_comb);
    cudaGetSymbolAddress((void**)&wcomb, g_wcomb);
    cudaGetSymbolAddress((void**)&actbf, g_actbf);

    init_state<<<(2*B_*H_ + 255)/256, 256>>>(hb, cb, alb, actbf);

    /* combined bf16 weights for the gates MMA */
    {
        size_t n = (size_t)G4H * KA;
        build_wcomb<<<(int)((n + 511)/512), 512>>>(W_ih, W_hh, wcomb);
    }

    gather_emb<<<U_*B_, 128>>>(emb_tab, label, emb);

    /* encoder-side projections (tf32 tensor GEMM) */
    tgemm_tn<<<dim3((T_*B_+63)/64, (E_+127)/128), 256>>>(Wh_m, E_, x, E_, nullptr,
            xh_m, 1, E_, E_, T_*B_, E_);
    tgemm_tn<<<dim3((T_*B_+63)/64, (E_+127)/128), 256>>>(Wh_c, E_, x, E_, nullptr,
            xh_c, 1, E_, E_, T_*B_, E_);

    /* eg = emb @ W_ih[:, :E]^T + b_lstm */
    tgemm_tn<<<dim3((U_*B_+63)/64, (G4H+127)/128), 256>>>(W_ih, 2*E_, emb, E_, b_lstm,
            eg, 1, G4H, G4H, U_*B_, E_);

    /* lm output */
    tgemm_tn<<<dim3((U_*B_+63)/64, (N_+127)/128), 256>>>(W_lm, E_, emb, E_, nullptr,
            out_lm, U_*B_, 1, N_, U_*B_, E_);

    /* folds: comb = [Ws_m@W_proj ; Ws_c@W_proj] (tf32) */
    transposeEH<<<dim3(H_/32, E_/32), dim3(32, 8)>>>(W_proj, wpT);
    tgemm_tn<<<dim3((H_+63)/64, (E_+127)/128), 256>>>(Ws_m, E_, wpT, E_, nullptr,
            comb, H_, 1, E_, H_, E_);
    tgemm_tn<<<dim3((H_+63)/64, (E_+127)/128), 256>>>(Ws_c, E_, wpT, E_, nullptr,
            comb + (size_t)E_*H_, H_, 1, E_, H_, E_);

    /* 48-step recurrence in one persistent kernel */
    decoder_loop<<<GRID, NT>>>(x, att_mask, wcomb, W_proj, comb,
            eg, v_m, v_c, r_m, xh_m, xh_c,
            gp, hb, cb, alb, actbf,
            sm, sc, p, uu, scall);

    /* am output */
    tgemm_tn<<<dim3((U_*B_+63)/64, (N_+127)/128), 256>>>(W_am, 2*E_, scall, 2*E_, nullptr,
            out_am, U_*B_, 1, N_, U_*B_, 2*E_);
}

// round 9
// speedup vs baseline: 1.0114x; 1.0114x over previous
#include <cuda_runtime.h>
#include <cuda_bf16.h>
#include <math.h>

#define T_ 256
#define B_ 16
#define E_ 512
#define H_ 2048
#define N_ 14839
#define U_ 48
#define G4H 8192
#define KA 2560              /* combined act length: 512 ctx + 2048 h */
#define KH (KA/2)            /* 1280, k-split half */
#define EPS_ 1e-6f
#define NT 256
#define GRID 296

/* ---------------- scratch ---------------- */
__device__ float g_xh_m[T_*B_*E_];
__device__ float g_xh_c[T_*B_*E_];
__device__ float g_emb[U_*B_*E_];
__device__ float g_eg[(size_t)U_*B_*G4H];
__device__ float g_gp[2][(size_t)B_*G4H];     /* k-split partial gates */
__device__ float g_h[2][B_*H_];
__device__ float g_c[2][B_*H_];
__device__ float g_alpha[2][T_*B_];
__device__ float g_sm[B_*E_];
__device__ float g_sc[B_*E_];
__device__ float g_p[T_*B_];
__device__ float g_u[T_*B_];
__device__ float g_scall[U_*B_*2*E_];
__device__ float g_wpT[H_*E_];
__device__ float g_comb[2*E_*H_];
__device__ __nv_bfloat16 g_wcomb[(size_t)G4H*KA];  /* [Wih_ctx | Whh] bf16 */
__device__ __nv_bfloat16 g_actbf[B_*KA];           /* [ctx | h] bf16 */

/* grid barrier state */
__device__ unsigned g_cnt = 0;
__device__ volatile unsigned g_gen = 0;

__device__ __forceinline__ void gbar() {
    __syncthreads();
    if (threadIdx.x == 0) {
        unsigned gen = g_gen;
        __threadfence();
        if (atomicAdd(&g_cnt, 1u) == gridDim.x - 1u) {
            g_cnt = 0;
            __threadfence();
            g_gen = gen + 1u;
        } else {
            while (g_gen == gen) __nanosleep(32);
        }
        __threadfence();
    }
    __syncthreads();
}

__device__ __forceinline__ float sigm(float x) { return 1.f / (1.f + expf(-x)); }
__device__ __forceinline__ float tanha(float x) {
    float y; asm("tanh.approx.f32 %0, %1;" : "=f"(y) : "f"(x)); return y;
}
__device__ __forceinline__ void bf8(float4 raw, float* o) {
    const __nv_bfloat162* p = (const __nv_bfloat162*)&raw;
    float2 a = __bfloat1622float2(p[0]); float2 b = __bfloat1622float2(p[1]);
    float2 c = __bfloat1622float2(p[2]); float2 d = __bfloat1622float2(p[3]);
    o[0]=a.x;o[1]=a.y;o[2]=b.x;o[3]=b.y;o[4]=c.x;o[5]=c.y;o[6]=d.x;o[7]=d.y;
}
__device__ __forceinline__ unsigned tf32c(float x) {
    unsigned r; asm("cvt.rna.tf32.f32 %0, %1;" : "=r"(r) : "f"(x)); return r;
}

/* ---------------- init ---------------- */
__global__ void init_state(float* h, float* c, float* alpha, __nv_bfloat16* actbf) {
    int i = blockIdx.x * blockDim.x + threadIdx.x;
    if (i < 2*B_*H_) { h[i] = 0.f; c[i] = 0.f; }
    if (i < B_*KA)   actbf[i] = __float2bfloat16(0.f);
    if (i < T_*B_)   alpha[i] = (i < B_) ? 1.f : 0.f;
}

/* ---------------- combined bf16 weight build ---------------- */
__global__ void build_wcomb(const float* __restrict__ W_ih, const float* __restrict__ W_hh,
                            __nv_bfloat16* __restrict__ wc) {
    size_t i = (size_t)blockIdx.x * blockDim.x + threadIdx.x;
    if (i >= (size_t)G4H * KA) return;
    int r = (int)(i / KA), k = (int)(i % KA);
    float v = (k < E_) ? W_ih[(size_t)r * (2*E_) + E_ + k]
                       : W_hh[(size_t)r * H_ + (k - E_)];
    wc[i] = __float2bfloat16(v);
}

/* ---------------- embedding gather ---------------- */
__global__ void gather_emb(const float* __restrict__ emb_table,
                           const int* __restrict__ label,
                           float* __restrict__ emb) {
    int r = blockIdx.x;
    int n = label[r];
    const float* src = emb_table + (size_t)n * E_;
    float* dst = emb + (size_t)r * E_;
    for (int i = threadIdx.x; i < E_; i += blockDim.x) dst[i] = src[i];
}

/* ---------------- transpose (512,2048) -> (2048,512) ---------------- */
__global__ void transposeEH(const float* __restrict__ A, float* __restrict__ At) {
    __shared__ float tile[32][33];
    int x0 = blockIdx.x * 32, y0 = blockIdx.y * 32;
    int tx = threadIdx.x, ty = threadIdx.y;
    for (int j = 0; j < 32; j += 8)
        tile[ty+j][tx] = A[(size_t)(y0+ty+j) * H_ + x0 + tx];
    __syncthreads();
    for (int j = 0; j < 32; j += 8)
        At[(size_t)(x0+ty+j) * E_ + y0 + tx] = tile[tx][ty+j];
}

/* ============ tf32 tensor-core GEMM (verified in R7) ============ */
#define TKC 32
#define TKP (TKC+4)
__global__ __launch_bounds__(256) void tgemm_tn(
        const float* __restrict__ W, int ldw,
        const float* __restrict__ X, int ldx,
        const float* __restrict__ bias,
        float* __restrict__ C, size_t ldcw, size_t ldcx,
        int M, int Nx, int K)
{
    __shared__ unsigned Ws[128][TKP];
    __shared__ unsigned Xs[64][TKP];
    int tid = threadIdx.x;
    int wid = tid >> 5, lane = tid & 31;
    int wm = (wid & 3) * 32;
    int wn = (wid >> 2) * 32;
    int m0 = blockIdx.y * 128;
    int n0 = blockIdx.x * 64;
    int g = lane >> 2, t = lane & 3;

    float c[2][4][4];
#pragma unroll
    for (int i = 0; i < 2; i++)
#pragma unroll
        for (int j = 0; j < 4; j++)
#pragma unroll
            for (int q = 0; q < 4; q++) c[i][j][q] = 0.f;

    for (int k0 = 0; k0 < K; k0 += TKC) {
        {
            int r = tid >> 1;
            int cc = (tid & 1) * 16;
#pragma unroll
            for (int i = 0; i < 4; i++) {
                float4 v = make_float4(0.f,0.f,0.f,0.f);
                if (m0 + r < M)
                    v = *(const float4*)(W + (size_t)(m0 + r) * ldw + k0 + cc + i*4);
                Ws[r][cc+i*4+0] = tf32c(v.x); Ws[r][cc+i*4+1] = tf32c(v.y);
                Ws[r][cc+i*4+2] = tf32c(v.z); Ws[r][cc+i*4+3] = tf32c(v.w);
            }
        }
        {
            int r = tid >> 2;
            int cc = (tid & 3) * 8;
#pragma unroll
            for (int i = 0; i < 2; i++) {
                float4 v = make_float4(0.f,0.f,0.f,0.f);
                if (n0 + r < Nx)
                    v = *(const float4*)(X + (size_t)(n0 + r) * ldx + k0 + cc + i*4);
                Xs[r][cc+i*4+0] = tf32c(v.x); Xs[r][cc+i*4+1] = tf32c(v.y);
                Xs[r][cc+i*4+2] = tf32c(v.z); Xs[r][cc+i*4+3] = tf32c(v.w);
            }
        }
        __syncthreads();

#pragma unroll
        for (int kk = 0; kk < TKC; kk += 8) {
            unsigned a[2][4];
#pragma unroll
            for (int mt = 0; mt < 2; mt++) {
                int br = wm + mt*16;
                a[mt][0] = Ws[br + g    ][kk + t];
                a[mt][1] = Ws[br + g + 8][kk + t];
                a[mt][2] = Ws[br + g    ][kk + t + 4];
                a[mt][3] = Ws[br + g + 8][kk + t + 4];
            }
            unsigned b[4][2];
#pragma unroll
            for (int nt = 0; nt < 4; nt++) {
                b[nt][0] = Xs[wn + nt*8 + g][kk + t];
                b[nt][1] = Xs[wn + nt*8 + g][kk + t + 4];
            }
#pragma unroll
            for (int mt = 0; mt < 2; mt++)
#pragma unroll
                for (int nt = 0; nt < 4; nt++) {
                    asm volatile(
                        "mma.sync.aligned.m16n8k8.row.col.f32.tf32.tf32.f32 "
                        "{%0,%1,%2,%3}, {%4,%5,%6,%7}, {%8,%9}, {%0,%1,%2,%3};"
                        : "+f"(c[mt][nt][0]), "+f"(c[mt][nt][1]),
                          "+f"(c[mt][nt][2]), "+f"(c[mt][nt][3])
                        : "r"(a[mt][0]), "r"(a[mt][1]), "r"(a[mt][2]), "r"(a[mt][3]),
                          "r"(b[nt][0]), "r"(b[nt][1]));
                }
        }
        __syncthreads();
    }

#pragma unroll
    for (int mt = 0; mt < 2; mt++) {
#pragma unroll
        for (int nt = 0; nt < 4; nt++) {
            int row0 = m0 + wm + mt*16 + g;
            int col0 = n0 + wn + nt*8 + 2*t;
#pragma unroll
            for (int half = 0; half < 2; half++) {
                int row = row0 + half*8;
                if (row >= M) continue;
                float bv = bias ? bias[row] : 0.f;
                if (col0 < Nx)
                    C[(size_t)row*ldcw + (size_t)col0*ldcx] = c[mt][nt][half*2+0] + bv;
                if (col0 + 1 < Nx)
                    C[(size_t)row*ldcw + (size_t)(col0+1)*ldcx] = c[mt][nt][half*2+1] + bv;
            }
        }
    }
}

/* ================ PERSISTENT DECODER LOOP ================ */
__global__ __launch_bounds__(NT) void decoder_loop(
        const float* __restrict__ x, const float* __restrict__ mask,
        const __nv_bfloat16* __restrict__ wcomb,
        const float* __restrict__ wproj, const float* __restrict__ comb,
        const float* __restrict__ eg,
        const float* __restrict__ v_m, const float* __restrict__ v_c,
        const float* __restrict__ r_m,
        const float* __restrict__ xh_m, const float* __restrict__ xh_c,
        float* gp, float* hb, float* cb, float* alb,
        __nv_bfloat16* actbf,
        float* smv, float* scv, float* pv, float* uvv,
        float* scall)
{
    __shared__ float shA[T_], shB[T_], shC[T_], shD[T_], shR[T_], shBeta[T_];
    int tid = threadIdx.x;
    int lane = tid & 31;
    int gw = blockIdx.x * (NT/32) + (tid >> 5);
    int NW = gridDim.x * (NT/32);
    int gtid = blockIdx.x * NT + tid;
    int NTH = gridDim.x * NT;

    for (int u = 0; u < U_; u++) {
        float*       h_out = hb + ((u&1)^1)*(B_*H_);
        const float* c_in  = cb + (u&1)*(B_*H_);
        float*       c_out = cb + ((u&1)^1)*(B_*H_);
        const float* al_in  = alb + (u&1)*(T_*B_);
        float*       al_out = alb + ((u&1)^1)*(T_*B_);
        const float* eg_u = eg + (size_t)u*B_*G4H;
        float*       sc_u = scall + (size_t)u*B_*(2*E_);

        /* ---- Phase A: partial gates, scalar bf16, k-split 2 for balance ----
           job = (row, half); gp[half][b*G4H + row] = sum_{k in half} act*w. */
        for (int job = gw; job < 2*G4H; job += NW) {
            int r = job >> 1, half = job & 1;
            const __nv_bfloat16* wr = wcomb + (size_t)r * KA + half*KH;
            const __nv_bfloat16* ab = actbf + half*KH;
            float acc[16];
#pragma unroll
            for (int b = 0; b < 16; b++) acc[b] = 0.f;
            for (int k = lane*8; k < KH; k += 256) {
                float wv[8]; bf8(*(const float4*)(wr + k), wv);
#pragma unroll
                for (int b = 0; b < 16; b++) {
                    float av[8]; bf8(*(const float4*)(ab + (size_t)b*KA + k), av);
                    acc[b] += wv[0]*av[0]+wv[1]*av[1]+wv[2]*av[2]+wv[3]*av[3]
                            + wv[4]*av[4]+wv[5]*av[5]+wv[6]*av[6]+wv[7]*av[7];
                }
            }
#pragma unroll
            for (int b = 0; b < 16; b++)
#pragma unroll
                for (int off = 16; off > 0; off >>= 1)
                    acc[b] += __shfl_xor_sync(0xffffffffu, acc[b], off);
            if (lane < 16)
                gp[(size_t)half*(B_*G4H) + (size_t)lane*G4H + r] = acc[lane];
        }
        gbar();

        /* ---- Phase B: sum partials + eg, LSTM pointwise; write h (fp32 + bf16) ---- */
        for (int i = gtid; i < B_*H_; i += NTH) {
            int b = i >> 11, k = i & (H_-1);
            size_t base = (size_t)b * G4H;
            const float* g0 = gp;
            const float* g1 = gp + (size_t)(B_*G4H);
            float gi = g0[base + k]        + g1[base + k]        + eg_u[base + k];
            float gf = g0[base + H_ + k]   + g1[base + H_ + k]   + eg_u[base + H_ + k];
            float gg = g0[base + 2*H_ + k] + g1[base + 2*H_ + k] + eg_u[base + 2*H_ + k];
            float go = g0[base + 3*H_ + k] + g1[base + 3*H_ + k] + eg_u[base + 3*H_ + k];
            float cn = sigm(gf) * c_in[i] + sigm(gi) * tanhf(gg);
            c_out[i] = cn;
            float hn = sigm(go) * tanhf(cn);
            h_out[i] = hn;
            actbf[(size_t)b * KA + E_ + k] = __float2bfloat16(hn);
        }
        gbar();

        /* ---- Phase C: s / sm / sc from h_new (fp32) ---- */
        for (int r = gw; r < 3*E_; r += NW) {
            const float* Wr = (r < E_) ? (wproj + (size_t)r * H_)
                                       : (comb + (size_t)(r - E_) * H_);
            float acc[16];
#pragma unroll
            for (int b = 0; b < 16; b++) acc[b] = 0.f;
            for (int k = lane*4; k < H_; k += 128) {
                float4 wv = *(const float4*)(Wr + k);
#pragma unroll
                for (int b = 0; b < 16; b++) {
                    float4 a = *(const float4*)(h_out + (size_t)b*H_ + k);
                    acc[b] += wv.x*a.x + wv.y*a.y + wv.z*a.z + wv.w*a.w;
                }
            }
#pragma unroll
            for (int b = 0; b < 16; b++)
#pragma unroll
                for (int off = 16; off > 0; off >>= 1)
                    acc[b] += __shfl_xor_sync(0xffffffffu, acc[b], off);
            if (lane < 16) {
                float v = acc[lane];
                if (r < E_)            sc_u[lane*(2*E_) + r] = v;
                else if (r < 2*E_)     smv[lane*E_ + (r - E_)] = v;
                else                   scv[lane*E_ + (r - 2*E_)] = v;
            }
        }
        gbar();

        /* ---- Phase D: energies ---- */
        for (int w = gw; w < T_*B_; w += NW) {
            int tt = w >> 4, b = w & 15;
            const float* xmp = xh_m + (size_t)(tt*B_ + b) * E_;
            const float* xcp = xh_c + (size_t)(tt*B_ + b) * E_;
            const float* smp = smv + (size_t)b * E_;
            const float* scp = scv + (size_t)b * E_;
            float am = 0.f, ac = 0.f;
            for (int e = lane*4; e < E_; e += 128) {
                float4 a  = *(const float4*)(xmp + e);
                float4 s4 = *(const float4*)(smp + e);
                float4 v4 = *(const float4*)(v_m + e);
                am += v4.x*tanha(a.x+s4.x) + v4.y*tanha(a.y+s4.y)
                    + v4.z*tanha(a.z+s4.z) + v4.w*tanha(a.w+s4.w);
                float4 a2  = *(const float4*)(xcp + e);
                float4 s42 = *(const float4*)(scp + e);
                float4 v42 = *(const float4*)(v_c + e);
                ac += v42.x*tanha(a2.x+s42.x) + v42.y*tanha(a2.y+s42.y)
                    + v42.z*tanha(a2.z+s42.z) + v42.w*tanha(a2.w+s42.w);
            }
#pragma unroll
            for (int off = 16; off > 0; off >>= 1) {
                am += __shfl_xor_sync(0xffffffffu, am, off);
                ac += __shfl_xor_sync(0xffffffffu, ac, off);
            }
            if (lane == 0) {
                float mk = mask[b*T_ + tt];
                pv[tt*B_ + b] = sigm(am + r_m[0]) * mk;
                uvv[tt*B_ + b] = ac;
            }
        }
        gbar();

        /* ---- Phase E+F: per-b scans then ctx (blocks 0..15) ---- */
        if (blockIdx.x < B_) {
            int b = blockIdx.x, tt = tid;
            float pvv = pv[tt*B_ + b];
            float uvl = uvv[tt*B_ + b];
            float ap  = al_in[tt*B_ + b];
            float mk  = mask[b*T_ + tt];

            shR[tt] = uvl; __syncthreads();
            for (int off = 128; off > 0; off >>= 1) {
                if (tt < off) shR[tt] = fmaxf(shR[tt], shR[tt+off]);
                __syncthreads();
            }
            float um = shR[0];

            float eu = expf(uvl - um) * mk;
            shA[tt] = eu; __syncthreads();
#pragma unroll
            for (int off = 1; off < T_; off <<= 1) {
                float xv = (tt >= off) ? shA[tt-off] : 0.f;
                __syncthreads(); shA[tt] += xv; __syncthreads();
            }
            float denom = shA[tt] - (tt >= 8 ? shA[tt-8] : 0.f);

            shB[tt] = 1.f - pvv; __syncthreads();
#pragma unroll
            for (int off = 1; off < T_; off <<= 1) {
                float xv = (tt >= off) ? shB[tt-off] : 1.f;
                __syncthreads(); shB[tt] *= xv; __syncthreads();
            }
            float cp = (tt == 0) ? 1.f : shB[tt-1];

            shC[tt] = ap / fmaxf(cp, EPS_); __syncthreads();
#pragma unroll
            for (int off = 1; off < T_; off <<= 1) {
                float xv = (tt >= off) ? shC[tt-off] : 0.f;
                __syncthreads(); shC[tt] += xv; __syncthreads();
            }
            float av = pvv * cp * shC[tt];

            shD[tt] = av / fmaxf(denom, EPS_); __syncthreads();
#pragma unroll
            for (int off = 1; off < T_; off <<= 1) {
                float xv = (tt >= off) ? shD[tt-off] : 0.f;
                __syncthreads(); shD[tt] += xv; __syncthreads();
            }
            int hi = (tt + 7 > T_-1) ? (T_-1) : (tt + 7);
            float bv = eu * (shD[hi] - (tt > 0 ? shD[tt-1] : 0.f));

            al_out[tt*B_ + b] = av;
            shBeta[tt] = bv;
            __syncthreads();

            for (int d = tid; d < E_; d += NT) {
                const float* xp = x + (size_t)b*E_ + d;
                float acc = 0.f;
#pragma unroll 8
                for (int q = 0; q < T_; q++)
                    acc += shBeta[q] * xp[(size_t)q * B_ * E_];
                sc_u[(size_t)b*(2*E_) + E_ + d] = acc;
                actbf[(size_t)b * KA + d] = __float2bfloat16(acc);
            }
        }
        gbar();
    }
}

/* ---------------- host launcher ---------------- */
extern "C" void kernel_launch(void* const* d_in, const int* in_sizes, int n_in,
                              void* d_out, int out_size)
{
    const float* x        = (const float*)d_in[0];
    const float* att_mask = (const float*)d_in[1];
    const float* emb_tab  = (const float*)d_in[2];
    const float* W_ih     = (const float*)d_in[3];
    const float* W_hh     = (const float*)d_in[4];
    const float* b_lstm   = (const float*)d_in[5];
    const float* W_proj   = (const float*)d_in[6];
    const float* Ws_m     = (const float*)d_in[7];
    const float* Wh_m     = (const float*)d_in[8];
    const float* v_m      = (const float*)d_in[9];
    const float* r_m      = (const float*)d_in[10];
    const float* Ws_c     = (const float*)d_in[11];
    const float* Wh_c     = (const float*)d_in[12];
    const float* v_c      = (const float*)d_in[13];
    const float* W_am     = (const float*)d_in[14];
    const float* W_lm     = (const float*)d_in[15];
    const int*   label    = (const int*)d_in[16];

    float* out_am = (float*)d_out;
    float* out_lm = out_am + (size_t)N_ * U_ * B_;

    float *xh_m, *xh_c, *emb, *eg, *gp, *hb, *cb, *alb, *sm, *sc, *p, *uu, *scall, *wpT, *comb;
    __nv_bfloat16 *wcomb, *actbf;
    cudaGetSymbolAddress((void**)&xh_m,  g_xh_m);
    cudaGetSymbolAddress((void**)&xh_c,  g_xh_c);
    cudaGetSymbolAddress((void**)&emb,   g_emb);
    cudaGetSymbolAddress((void**)&eg,    g_eg);
    cudaGetSymbolAddress((void**)&gp,    g_gp);
    cudaGetSymbolAddress((void**)&hb,    g_h);
    cudaGetSymbolAddress((void**)&cb,    g_c);
    cudaGetSymbolAddress((void**)&alb,   g_alpha);
    cudaGetSymbolAddress((void**)&sm,    g_sm);
    cudaGetSymbolAddress((void**)&sc,    g_sc);
    cudaGetSymbolAddress((void**)&p,     g_p);
    cudaGetSymbolAddress((void**)&uu,    g_u);
    cudaGetSymbolAddress((void**)&scall, g_scall);
    cudaGetSymbolAddress((void**)&wpT,   g_wpT);
    cudaGetSymbolAddress((void**)&comb,  g_comb);
    cudaGetSymbolAddress((void**)&wcomb, g_wcomb);
    cudaGetSymbolAddress((void**)&actbf, g_actbf);

    init_state<<<(2*B_*H_ + 255)/256, 256>>>(hb, cb, alb, actbf);

    {
        size_t n = (size_t)G4H * KA;
        build_wcomb<<<(int)((n + 511)/512), 512>>>(W_ih, W_hh, wcomb);
    }

    gather_emb<<<U_*B_, 128>>>(emb_tab, label, emb);

    /* encoder-side projections (tf32 tensor GEMM) */
    tgemm_tn<<<dim3((T_*B_+63)/64, (E_+127)/128), 256>>>(Wh_m, E_, x, E_, nullptr,
            xh_m, 1, E_, E_, T_*B_, E_);
    tgemm_tn<<<dim3((T_*B_+63)/64, (E_+127)/128), 256>>>(Wh_c, E_, x, E_, nullptr,
            xh_c, 1, E_, E_, T_*B_, E_);

    /* eg = emb @ W_ih[:, :E]^T + b_lstm */
    tgemm_tn<<<dim3((U_*B_+63)/64, (G4H+127)/128), 256>>>(W_ih, 2*E_, emb, E_, b_lstm,
            eg, 1, G4H, G4H, U_*B_, E_);

    /* lm output */
    tgemm_tn<<<dim3((U_*B_+63)/64, (N_+127)/128), 256>>>(W_lm, E_, emb, E_, nullptr,
            out_lm, U_*B_, 1, N_, U_*B_, E_);

    /* folds: comb = [Ws_m@W_proj ; Ws_c@W_proj] (tf32) */
    transposeEH<<<dim3(H_/32, E_/32), dim3(32, 8)>>>(W_proj, wpT);
    tgemm_tn<<<dim3((H_+63)/64, (E_+127)/128), 256>>>(Ws_m, E_, wpT, E_, nullptr,
            comb, H_, 1, E_, H_, E_);
    tgemm_tn<<<dim3((H_+63)/64, (E_+127)/128), 256>>>(Ws_c, E_, wpT, E_, nullptr,
            comb + (size_t)E_*H_, H_, 1, E_, H_, E_);

    /* 48-step recurrence in one persistent kernel */
    decoder_loop<<<GRID, NT>>>(x, att_mask, wcomb, W_proj, comb,
            eg, v_m, v_c, r_m, xh_m, xh_c,
            gp, hb, cb, alb, actbf,
            sm, sc, p, uu, scall);

    /* am output */
    tgemm_tn<<<dim3((U_*B_+63)/64, (N_+127)/128), 256>>>(W_am, 2*E_, scall, 2*E_, nullptr,
            out_am, U_*B_, 1, N_, U_*B_, 2*E_);
}

// round 10
// speedup vs baseline: 1.0539x; 1.0420x over previous
#include <cuda_runtime.h>
#include <cuda_bf16.h>
#include <math.h>

#define T_ 256
#define B_ 16
#define E_ 512
#define H_ 2048
#define N_ 14839
#define U_ 48
#define G4H 8192
#define EPS_ 1e-6f
#define NT 256
#define GRID 256

/* ---------------- scratch ---------------- */
__device__ float g_xh_m[T_*B_*E_];
__device__ float g_xh_c[T_*B_*E_];
__device__ float g_emb[U_*B_*E_];
__device__ float g_eg[(size_t)U_*B_*G4H];
__device__ float g_gates[(size_t)B_*G4H];
__device__ float g_h[2][B_*H_];
__device__ float g_c[2][B_*H_];
__device__ float g_alpha[2][T_*B_];
__device__ float g_sm[B_*E_];
__device__ float g_sc[B_*E_];
__device__ float g_p[T_*B_];
__device__ float g_u[T_*B_];
__device__ float g_beta[T_*B_];
__device__ float g_scall[U_*B_*2*E_];
__device__ float g_wpT[H_*E_];
__device__ float g_comb[2*E_*H_];
__device__ __nv_bfloat16 g_whh_bf[(size_t)G4H*H_];
__device__ __nv_bfloat16 g_wihc_bf[(size_t)G4H*E_];
__device__ __nv_bfloat16 g_hbf[B_*H_];
__device__ __nv_bfloat16 g_ctxbf[B_*E_];

/* grid barrier state */
__device__ unsigned g_cnt = 0;
__device__ volatile unsigned g_gen = 0;

__device__ __forceinline__ void gbar() {
    __syncthreads();
    if (threadIdx.x == 0) {
        unsigned gen = g_gen;
        __threadfence();
        if (atomicAdd(&g_cnt, 1u) == gridDim.x - 1u) {
            g_cnt = 0;
            __threadfence();
            g_gen = gen + 1u;
        } else {
            while (g_gen == gen) __nanosleep(32);
        }
        __threadfence();
    }
    __syncthreads();
}

__device__ __forceinline__ float sigm(float x) { return 1.f / (1.f + expf(-x)); }
__device__ __forceinline__ float tanha(float x) {
    float y; asm("tanh.approx.f32 %0, %1;" : "=f"(y) : "f"(x)); return y;
}
__device__ __forceinline__ void bf8(float4 raw, float* o) {
    const __nv_bfloat162* p = (const __nv_bfloat162*)&raw;
    float2 a = __bfloat1622float2(p[0]); float2 b = __bfloat1622float2(p[1]);
    float2 c = __bfloat1622float2(p[2]); float2 d = __bfloat1622float2(p[3]);
    o[0]=a.x;o[1]=a.y;o[2]=b.x;o[3]=b.y;o[4]=c.x;o[5]=c.y;o[6]=d.x;o[7]=d.y;
}
__device__ __forceinline__ unsigned tf32c(float x) {
    unsigned r; asm("cvt.rna.tf32.f32 %0, %1;" : "=r"(r) : "f"(x)); return r;
}

/* ---------------- init ---------------- */
__global__ void init_state(float* h, float* c, float* alpha,
                           __nv_bfloat16* hbf, __nv_bfloat16* ctxbf) {
    int i = blockIdx.x * blockDim.x + threadIdx.x;
    if (i < 2*B_*H_) { h[i] = 0.f; c[i] = 0.f; }
    if (i < B_*H_)   hbf[i] = __float2bfloat16(0.f);
    if (i < B_*E_)   ctxbf[i] = __float2bfloat16(0.f);
    if (i < T_*B_)   alpha[i] = (i < B_) ? 1.f : 0.f;
}

/* ---------------- conversions ---------------- */
__global__ void f2bf(const float* __restrict__ src, __nv_bfloat16* __restrict__ dst, size_t n) {
    size_t i = (size_t)blockIdx.x * blockDim.x + threadIdx.x;
    if (i < n) dst[i] = __float2bfloat16(src[i]);
}
__global__ void f2bf_strided(const float* __restrict__ src, int ld, int off,
                             __nv_bfloat16* __restrict__ dst, int cols, size_t n) {
    size_t i = (size_t)blockIdx.x * blockDim.x + threadIdx.x;
    if (i >= n) return;
    size_t r = i / cols, c = i % cols;
    dst[i] = __float2bfloat16(src[r * (size_t)ld + off + c]);
}

/* ---------------- embedding gather ---------------- */
__global__ void gather_emb(const float* __restrict__ emb_table,
                           const int* __restrict__ label,
                           float* __restrict__ emb) {
    int r = blockIdx.x;
    int n = label[r];
    const float* src = emb_table + (size_t)n * E_;
    float* dst = emb + (size_t)r * E_;
    for (int i = threadIdx.x; i < E_; i += blockDim.x) dst[i] = src[i];
}

/* ---------------- transpose (512,2048) -> (2048,512) ---------------- */
__global__ void transposeEH(const float* __restrict__ A, float* __restrict__ At) {
    __shared__ float tile[32][33];
    int x0 = blockIdx.x * 32, y0 = blockIdx.y * 32;
    int tx = threadIdx.x, ty = threadIdx.y;
    for (int j = 0; j < 32; j += 8)
        tile[ty+j][tx] = A[(size_t)(y0+ty+j) * H_ + x0 + tx];
    __syncthreads();
    for (int j = 0; j < 32; j += 8)
        At[(size_t)(x0+ty+j) * E_ + y0 + tx] = tile[tx][ty+j];
}

/* ============ tf32 tensor-core GEMM with register-prefetch pipeline ============ */
#define TKC 32
#define TKP (TKC+4)
__global__ __launch_bounds__(256) void tgemm_tn(
        const float* __restrict__ W, int ldw,
        const float* __restrict__ X, int ldx,
        const float* __restrict__ bias,
        float* __restrict__ C, size_t ldcw, size_t ldcx,
        int M, int Nx, int K)
{
    __shared__ unsigned Ws[128][TKP];
    __shared__ unsigned Xs[64][TKP];
    int tid = threadIdx.x;
    int wid = tid >> 5, lane = tid & 31;
    int wm = (wid & 3) * 32;
    int wn = (wid >> 2) * 32;
    int m0 = blockIdx.y * 128;
    int n0 = blockIdx.x * 64;
    int g = lane >> 2, t = lane & 3;

    int wrow = tid >> 1, wcol = (tid & 1) * 16;     // W stage coords
    int xrow = tid >> 2, xcol = (tid & 3) * 8;      // X stage coords

    float4 wreg[4], xreg[2];

    /* prologue: fetch tile 0 */
#pragma unroll
    for (int i = 0; i < 4; i++) {
        wreg[i] = make_float4(0.f,0.f,0.f,0.f);
        if (m0 + wrow < M)
            wreg[i] = *(const float4*)(W + (size_t)(m0 + wrow) * ldw + wcol + i*4);
    }
#pragma unroll
    for (int i = 0; i < 2; i++) {
        xreg[i] = make_float4(0.f,0.f,0.f,0.f);
        if (n0 + xrow < Nx)
            xreg[i] = *(const float4*)(X + (size_t)(n0 + xrow) * ldx + xcol + i*4);
    }

    float c[2][4][4];
#pragma unroll
    for (int i = 0; i < 2; i++)
#pragma unroll
        for (int j = 0; j < 4; j++)
#pragma unroll
            for (int q = 0; q < 4; q++) c[i][j][q] = 0.f;

    for (int k0 = 0; k0 < K; k0 += TKC) {
        /* commit staged regs to smem (with tf32 cvt) */
#pragma unroll
        for (int i = 0; i < 4; i++) {
            Ws[wrow][wcol+i*4+0] = tf32c(wreg[i].x); Ws[wrow][wcol+i*4+1] = tf32c(wreg[i].y);
            Ws[wrow][wcol+i*4+2] = tf32c(wreg[i].z); Ws[wrow][wcol+i*4+3] = tf32c(wreg[i].w);
        }
#pragma unroll
        for (int i = 0; i < 2; i++) {
            Xs[xrow][xcol+i*4+0] = tf32c(xreg[i].x); Xs[xrow][xcol+i*4+1] = tf32c(xreg[i].y);
            Xs[xrow][xcol+i*4+2] = tf32c(xreg[i].z); Xs[xrow][xcol+i*4+3] = tf32c(xreg[i].w);
        }
        __syncthreads();

        /* prefetch next tile into regs (overlaps with MMA below) */
        int k1 = k0 + TKC;
        if (k1 < K) {
#pragma unroll
            for (int i = 0; i < 4; i++) {
                wreg[i] = make_float4(0.f,0.f,0.f,0.f);
                if (m0 + wrow < M)
                    wreg[i] = *(const float4*)(W + (size_t)(m0 + wrow) * ldw + k1 + wcol + i*4);
            }
#pragma unroll
            for (int i = 0; i < 2; i++) {
                xreg[i] = make_float4(0.f,0.f,0.f,0.f);
                if (n0 + xrow < Nx)
                    xreg[i] = *(const float4*)(X + (size_t)(n0 + xrow) * ldx + k1 + xcol + i*4);
            }
        }

#pragma unroll
        for (int kk = 0; kk < TKC; kk += 8) {
            unsigned a[2][4];
#pragma unroll
            for (int mt = 0; mt < 2; mt++) {
                int br = wm + mt*16;
                a[mt][0] = Ws[br + g    ][kk + t];
                a[mt][1] = Ws[br + g + 8][kk + t];
                a[mt][2] = Ws[br + g    ][kk + t + 4];
                a[mt][3] = Ws[br + g + 8][kk + t + 4];
            }
            unsigned b[4][2];
#pragma unroll
            for (int nt = 0; nt < 4; nt++) {
                b[nt][0] = Xs[wn + nt*8 + g][kk + t];
                b[nt][1] = Xs[wn + nt*8 + g][kk + t + 4];
            }
#pragma unroll
            for (int mt = 0; mt < 2; mt++)
#pragma unroll
                for (int nt = 0; nt < 4; nt++) {
                    asm volatile(
                        "mma.sync.aligned.m16n8k8.row.col.f32.tf32.tf32.f32 "
                        "{%0,%1,%2,%3}, {%4,%5,%6,%7}, {%8,%9}, {%0,%1,%2,%3};"
                        : "+f"(c[mt][nt][0]), "+f"(c[mt][nt][1]),
                          "+f"(c[mt][nt][2]), "+f"(c[mt][nt][3])
                        : "r"(a[mt][0]), "r"(a[mt][1]), "r"(a[mt][2]), "r"(a[mt][3]),
                          "r"(b[nt][0]), "r"(b[nt][1]));
                }
        }
        __syncthreads();
    }

#pragma unroll
    for (int mt = 0; mt < 2; mt++) {
#pragma unroll
        for (int nt = 0; nt < 4; nt++) {
            int row0 = m0 + wm + mt*16 + g;
            int col0 = n0 + wn + nt*8 + 2*t;
#pragma unroll
            for (int half = 0; half < 2; half++) {
                int row = row0 + half*8;
                if (row >= M) continue;
                float bv = bias ? bias[row] : 0.f;
                if (col0 < Nx)
                    C[(size_t)row*ldcw + (size_t)col0*ldcx] = c[mt][nt][half*2+0] + bv;
                if (col0 + 1 < Nx)
                    C[(size_t)row*ldcw + (size_t)(col0+1)*ldcx] = c[mt][nt][half*2+1] + bv;
            }
        }
    }
}

/* ================ PERSISTENT DECODER LOOP (R7-proven configuration) ================ */
__global__ __launch_bounds__(NT) void decoder_loop(
        const float* __restrict__ x, const float* __restrict__ mask,
        const __nv_bfloat16* __restrict__ whh, const __nv_bfloat16* __restrict__ wihc,
        const float* __restrict__ wproj, const float* __restrict__ comb,
        const float* __restrict__ eg,
        const float* __restrict__ v_m, const float* __restrict__ v_c,
        const float* __restrict__ r_m,
        const float* __restrict__ xh_m, const float* __restrict__ xh_c,
        float* gates, float* hb, float* cb, float* alb,
        __nv_bfloat16* hbf, __nv_bfloat16* ctxbf,
        float* smv, float* scv, float* pv, float* uvv, float* betav,
        float* scall)
{
    __shared__ float shA[T_], shB[T_], shC[T_], shD[T_], shR[T_];
    int tid = threadIdx.x;
    int lane = tid & 31;
    int gw = blockIdx.x * (NT/32) + (tid >> 5);
    int NW = gridDim.x * (NT/32);
    int gtid = blockIdx.x * NT + tid;
    int NTH = gridDim.x * NT;

    for (int u = 0; u < U_; u++) {
        float*       h_out = hb + ((u&1)^1)*(B_*H_);
        const float* c_in  = cb + (u&1)*(B_*H_);
        float*       c_out = cb + ((u&1)^1)*(B_*H_);
        const float* al_in  = alb + (u&1)*(T_*B_);
        float*       al_out = alb + ((u&1)^1)*(T_*B_);
        const float* eg_u = eg + (size_t)u*B_*G4H;
        float*       sc_u = scall + (size_t)u*B_*(2*E_);

        /* ---- Phase A: gates (scalar bf16, 4 rows/warp exactly) ---- */
        for (int r = gw; r < G4H; r += NW) {
            float acc[16];
#pragma unroll
            for (int b = 0; b < 16; b++) acc[b] = 0.f;
            {
                const __nv_bfloat16* wr = wihc + (size_t)r * E_;
                for (int k = lane*8; k < E_; k += 256) {
                    float wv[8]; bf8(*(const float4*)(wr + k), wv);
#pragma unroll
                    for (int b = 0; b < 16; b++) {
                        float av[8]; bf8(*(const float4*)(ctxbf + b*E_ + k), av);
                        acc[b] += wv[0]*av[0]+wv[1]*av[1]+wv[2]*av[2]+wv[3]*av[3]
                                + wv[4]*av[4]+wv[5]*av[5]+wv[6]*av[6]+wv[7]*av[7];
                    }
                }
            }
            {
                const __nv_bfloat16* wr = whh + (size_t)r * H_;
                for (int k = lane*8; k < H_; k += 256) {
                    float wv[8]; bf8(*(const float4*)(wr + k), wv);
#pragma unroll
                    for (int b = 0; b < 16; b++) {
                        float av[8]; bf8(*(const float4*)(hbf + b*H_ + k), av);
                        acc[b] += wv[0]*av[0]+wv[1]*av[1]+wv[2]*av[2]+wv[3]*av[3]
                                + wv[4]*av[4]+wv[5]*av[5]+wv[6]*av[6]+wv[7]*av[7];
                    }
                }
            }
#pragma unroll
            for (int b = 0; b < 16; b++)
#pragma unroll
                for (int off = 16; off > 0; off >>= 1)
                    acc[b] += __shfl_xor_sync(0xffffffffu, acc[b], off);
            if (lane < 16)
                gates[(size_t)lane*G4H + r] = acc[lane] + eg_u[(size_t)lane*G4H + r];
        }
        gbar();

        /* ---- Phase B: LSTM pointwise ---- */
        for (int i = gtid; i < B_*H_; i += NTH) {
            int b = i >> 11, k = i & (H_-1);
            const float* g = gates + (size_t)b * G4H;
            float gi = g[k], gf = g[H_ + k], gg = g[2*H_ + k], go = g[3*H_ + k];
            float cn = sigm(gf) * c_in[i] + sigm(gi) * tanhf(gg);
            c_out[i] = cn;
            float hn = sigm(go) * tanhf(cn);
            h_out[i] = hn;
            hbf[i] = __float2bfloat16(hn);
        }
        gbar();

        /* ---- Phase C: s / sm / sc ---- */
        for (int r = gw; r < 3*E_; r += NW) {
            const float* Wr = (r < E_) ? (wproj + (size_t)r * H_)
                                       : (comb + (size_t)(r - E_) * H_);
            float acc[16];
#pragma unroll
            for (int b = 0; b < 16; b++) acc[b] = 0.f;
            for (int k = lane*4; k < H_; k += 128) {
                float4 wv = *(const float4*)(Wr + k);
#pragma unroll
                for (int b = 0; b < 16; b++) {
                    float4 a = *(const float4*)(h_out + (size_t)b*H_ + k);
                    acc[b] += wv.x*a.x + wv.y*a.y + wv.z*a.z + wv.w*a.w;
                }
            }
#pragma unroll
            for (int b = 0; b < 16; b++)
#pragma unroll
                for (int off = 16; off > 0; off >>= 1)
                    acc[b] += __shfl_xor_sync(0xffffffffu, acc[b], off);
            if (lane < 16) {
                float v = acc[lane];
                if (r < E_)            sc_u[lane*(2*E_) + r] = v;
                else if (r < 2*E_)     smv[lane*E_ + (r - E_)] = v;
                else                   scv[lane*E_ + (r - 2*E_)] = v;
            }
        }
        gbar();

        /* ---- Phase D: energies ---- */
        for (int w = gw; w < T_*B_; w += NW) {
            int tt = w >> 4, b = w & 15;
            const float* xmp = xh_m + (size_t)(tt*B_ + b) * E_;
            const float* xcp = xh_c + (size_t)(tt*B_ + b) * E_;
            const float* smp = smv + (size_t)b * E_;
            const float* scp = scv + (size_t)b * E_;
            float am = 0.f, ac = 0.f;
            for (int e = lane*4; e < E_; e += 128) {
                float4 a  = *(const float4*)(xmp + e);
                float4 s4 = *(const float4*)(smp + e);
                float4 v4 = *(const float4*)(v_m + e);
                am += v4.x*tanha(a.x+s4.x) + v4.y*tanha(a.y+s4.y)
                    + v4.z*tanha(a.z+s4.z) + v4.w*tanha(a.w+s4.w);
                float4 a2  = *(const float4*)(xcp + e);
                float4 s42 = *(const float4*)(scp + e);
                float4 v42 = *(const float4*)(v_c + e);
                ac += v42.x*tanha(a2.x+s42.x) + v42.y*tanha(a2.y+s42.y)
                    + v42.z*tanha(a2.z+s42.z) + v42.w*tanha(a2.w+s42.w);
            }
#pragma unroll
            for (int off = 16; off > 0; off >>= 1) {
                am += __shfl_xor_sync(0xffffffffu, am, off);
                ac += __shfl_xor_sync(0xffffffffu, ac, off);
            }
            if (lane == 0) {
                float mk = mask[b*T_ + tt];
                pv[tt*B_ + b] = sigm(am + r_m[0]) * mk;
                uvv[tt*B_ + b] = ac;
            }
        }
        gbar();

        /* ---- Phase E: per-b scans ---- */
        if (blockIdx.x < B_) {
            int b = blockIdx.x, tt = tid;
            float pvv = pv[tt*B_ + b];
            float uvl = uvv[tt*B_ + b];
            float ap  = al_in[tt*B_ + b];
            float mk  = mask[b*T_ + tt];

            shR[tt] = uvl; __syncthreads();
            for (int off = 128; off > 0; off >>= 1) {
                if (tt < off) shR[tt] = fmaxf(shR[tt], shR[tt+off]);
                __syncthreads();
            }
            float um = shR[0];

            float eu = expf(uvl - um) * mk;
            shA[tt] = eu; __syncthreads();
#pragma unroll
            for (int off = 1; off < T_; off <<= 1) {
                float xv = (tt >= off) ? shA[tt-off] : 0.f;
                __syncthreads(); shA[tt] += xv; __syncthreads();
            }
            float denom = shA[tt] - (tt >= 8 ? shA[tt-8] : 0.f);

            shB[tt] = 1.f - pvv; __syncthreads();
#pragma unroll
            for (int off = 1; off < T_; off <<= 1) {
                float xv = (tt >= off) ? shB[tt-off] : 1.f;
                __syncthreads(); shB[tt] *= xv; __syncthreads();
            }
            float cp = (tt == 0) ? 1.f : shB[tt-1];

            shC[tt] = ap / fmaxf(cp, EPS_); __syncthreads();
#pragma unroll
            for (int off = 1; off < T_; off <<= 1) {
                float xv = (tt >= off) ? shC[tt-off] : 0.f;
                __syncthreads(); shC[tt] += xv; __syncthreads();
            }
            float av = pvv * cp * shC[tt];

            shD[tt] = av / fmaxf(denom, EPS_); __syncthreads();
#pragma unroll
            for (int off = 1; off < T_; off <<= 1) {
                float xv = (tt >= off) ? shD[tt-off] : 0.f;
                __syncthreads(); shD[tt] += xv; __syncthreads();
            }
            int hi = (tt + 7 > T_-1) ? (T_-1) : (tt + 7);
            float bv = eu * (shD[hi] - (tt > 0 ? shD[tt-1] : 0.f));

            al_out[tt*B_ + b] = av;
            betav[tt*B_ + b] = bv;
        }
        gbar();

        /* ---- Phase F: ctx ---- */
        for (int i = gtid; i < B_*E_; i += NTH) {
            int b = i >> 9, d = i & (E_-1);
            const float* xp = x + (size_t)b*E_ + d;
            float acc = 0.f;
#pragma unroll 8
            for (int tq = 0; tq < T_; tq++)
                acc += betav[tq*B_ + b] * xp[(size_t)tq * B_ * E_];
            sc_u[(size_t)b*(2*E_) + E_ + d] = acc;
            ctxbf[i] = __float2bfloat16(acc);
        }
        gbar();
    }
}

/* ---------------- host launcher ---------------- */
extern "C" void kernel_launch(void* const* d_in, const int* in_sizes, int n_in,
                              void* d_out, int out_size)
{
    const float* x        = (const float*)d_in[0];
    const float* att_mask = (const float*)d_in[1];
    const float* emb_tab  = (const float*)d_in[2];
    const float* W_ih     = (const float*)d_in[3];
    const float* W_hh     = (const float*)d_in[4];
    const float* b_lstm   = (const float*)d_in[5];
    const float* W_proj   = (const float*)d_in[6];
    const float* Ws_m     = (const float*)d_in[7];
    const float* Wh_m     = (const float*)d_in[8];
    const float* v_m      = (const float*)d_in[9];
    const float* r_m      = (const float*)d_in[10];
    const float* Ws_c     = (const float*)d_in[11];
    const float* Wh_c     = (const float*)d_in[12];
    const float* v_c      = (const float*)d_in[13];
    const float* W_am     = (const float*)d_in[14];
    const float* W_lm     = (const float*)d_in[15];
    const int*   label    = (const int*)d_in[16];

    float* out_am = (float*)d_out;
    float* out_lm = out_am + (size_t)N_ * U_ * B_;

    float *xh_m, *xh_c, *emb, *eg, *gates, *hb, *cb, *alb, *sm, *sc, *p, *uu, *beta, *scall, *wpT, *comb;
    __nv_bfloat16 *whh_bf, *wihc_bf, *hbf, *ctxbf;
    cudaGetSymbolAddress((void**)&xh_m,  g_xh_m);
    cudaGetSymbolAddress((void**)&xh_c,  g_xh_c);
    cudaGetSymbolAddress((void**)&emb,   g_emb);
    cudaGetSymbolAddress((void**)&eg,    g_eg);
    cudaGetSymbolAddress((void**)&gates, g_gates);
    cudaGetSymbolAddress((void**)&hb,    g_h);
    cudaGetSymbolAddress((void**)&cb,    g_c);
    cudaGetSymbolAddress((void**)&alb,   g_alpha);
    cudaGetSymbolAddress((void**)&sm,    g_sm);
    cudaGetSymbolAddress((void**)&sc,    g_sc);
    cudaGetSymbolAddress((void**)&p,     g_p);
    cudaGetSymbolAddress((void**)&uu,    g_u);
    cudaGetSymbolAddress((void**)&beta,  g_beta);
    cudaGetSymbolAddress((void**)&scall, g_scall);
    cudaGetSymbolAddress((void**)&wpT,   g_wpT);
    cudaGetSymbolAddress((void**)&comb,  g_comb);
    cudaGetSymbolAddress((void**)&whh_bf,  g_whh_bf);
    cudaGetSymbolAddress((void**)&wihc_bf, g_wihc_bf);
    cudaGetSymbolAddress((void**)&hbf,   g_hbf);
    cudaGetSymbolAddress((void**)&ctxbf, g_ctxbf);

    init_state<<<(2*B_*H_ + 255)/256, 256>>>(hb, cb, alb, hbf, ctxbf);

    {
        size_t n;
        n = (size_t)G4H*H_; f2bf<<<(int)((n+511)/512), 512>>>(W_hh, whh_bf, n);
        n = (size_t)G4H*E_; f2bf_strided<<<(int)((n+511)/512), 512>>>(W_ih, 2*E_, E_, wihc_bf, E_, n);
    }

    gather_emb<<<U_*B_, 128>>>(emb_tab, label, emb);

    /* encoder-side projections (tf32 tensor GEMM, pipelined) */
    tgemm_tn<<<dim3((T_*B_+63)/64, (E_+127)/128), 256>>>(Wh_m, E_, x, E_, nullptr,
            xh_m, 1, E_, E_, T_*B_, E_);
    tgemm_tn<<<dim3((T_*B_+63)/64, (E_+127)/128), 256>>>(Wh_c, E_, x, E_, nullptr,
            xh_c, 1, E_, E_, T_*B_, E_);

    /* eg = emb @ W_ih[:, :E]^T + b_lstm */
    tgemm_tn<<<dim3((U_*B_+63)/64, (G4H+127)/128), 256>>>(W_ih, 2*E_, emb, E_, b_lstm,
            eg, 1, G4H, G4H, U_*B_, E_);

    /* lm output */
    tgemm_tn<<<dim3((U_*B_+63)/64, (N_+127)/128), 256>>>(W_lm, E_, emb, E_, nullptr,
            out_lm, U_*B_, 1, N_, U_*B_, E_);

    /* folds: comb = [Ws_m@W_proj ; Ws_c@W_proj] (tf32) */
    transposeEH<<<dim3(H_/32, E_/32), dim3(32, 8)>>>(W_proj, wpT);
    tgemm_tn<<<dim3((H_+63)/64, (E_+127)/128), 256>>>(Ws_m, E_, wpT, E_, nullptr,
            comb, H_, 1, E_, H_, E_);
    tgemm_tn<<<dim3((H_+63)/64, (E_+127)/128), 256>>>(Ws_c, E_, wpT, E_, nullptr,
            comb + (size_t)E_*H_, H_, 1, E_, H_, E_);

    /* 48-step recurrence in one persistent kernel */
    decoder_loop<<<GRID, NT>>>(x, att_mask, whh_bf, wihc_bf, W_proj, comb,
            eg, v_m, v_c, r_m, xh_m, xh_c,
            gates, hb, cb, alb, hbf, ctxbf,
            sm, sc, p, uu, beta, scall);

    /* am output */
    tgemm_tn<<<dim3((U_*B_+63)/64, (N_+127)/128), 256>>>(W_am, 2*E_, scall, 2*E_, nullptr,
            out_am, U_*B_, 1, N_, U_*B_, 2*E_);
}